// round 14
// baseline (speedup 1.0000x reference)
#include <cuda_runtime.h>
#include <cuda_bf16.h>
#include <math.h>
#include <stdint.h>

// Problem constants
#define BB   2
#define TT   2048
#define DD   1024
#define LL   4
#define HH   16
#define HD   64
#define VV   32000
#define DFF  4096
#define MM   (BB*TT)        // 4096 rows
#define QKVD 3072

// ---------------------------------------------------------------------------
// Scratch (device globals; allocation is forbidden). 256B aligned for bulk.
// Tiled bf16 layout everywhere: [row/128][k/32] tiles of 128 rows x 40 elems
// (32 data + 8 pad) = 5120 elems = 10240 B contiguous  ==  the smem image.
// ---------------------------------------------------------------------------
__device__ __align__(256) float g_x  [MM*DD];
__device__ __align__(256) float g_qkv[MM*QKVD];

__device__ __align__(256) __nv_bfloat16 g_ah[(MM/128)*(DD/32)*5120],  g_al[(MM/128)*(DD/32)*5120];
__device__ __align__(256) __nv_bfloat16 g_fh[(MM/128)*(DFF/32)*5120], g_fl[(MM/128)*(DFF/32)*5120];

__device__ __align__(256) __nv_bfloat16 g_wqkvh[(QKVD/128)*(DD/32)*5120*LL], g_wqkvl[(QKVD/128)*(DD/32)*5120*LL];
__device__ __align__(256) __nv_bfloat16 g_woh  [(DD/128)*(DD/32)*5120*LL],   g_wol  [(DD/128)*(DD/32)*5120*LL];
__device__ __align__(256) __nv_bfloat16 g_w1h  [(DFF/128)*(DD/32)*5120*LL],  g_w1l  [(DFF/128)*(DD/32)*5120*LL];
__device__ __align__(256) __nv_bfloat16 g_w2h  [(DD/128)*(DFF/32)*5120*LL],  g_w2l  [(DD/128)*(DFF/32)*5120*LL];
__device__ __align__(256) __nv_bfloat16 g_wouth[(VV/128)*(DD/32)*5120],      g_woutl[(VV/128)*(DD/32)*5120];

// tiled offset: element index for (row, k) with K/32 chunks per row-tile
__device__ __forceinline__ size_t tiled_off(int row, int k, int kdiv32) {
    return ((size_t)(row >> 7) * kdiv32 + (k >> 5)) * 5120
         + (size_t)((row & 127) * 40 + (k & 31));
}

// ---------------------------------------------------------------------------
// PTX helpers (sm_90 base ISA; no 'a'-suffix features)
// ---------------------------------------------------------------------------
__device__ __forceinline__ uint32_t smem_u32(const void* p) {
    return (uint32_t)__cvta_generic_to_shared(p);
}
__device__ __forceinline__ void ldmat_x4(uint32_t* r, uint32_t addr) {
    asm volatile("ldmatrix.sync.aligned.m8n8.x4.shared.b16 {%0,%1,%2,%3}, [%4];"
                 : "=r"(r[0]), "=r"(r[1]), "=r"(r[2]), "=r"(r[3]) : "r"(addr));
}
__device__ __forceinline__ void mma16816(float* d, const uint32_t* a,
                                         const uint32_t* b) {
    asm volatile(
        "mma.sync.aligned.m16n8k16.row.col.f32.bf16.bf16.f32 "
        "{%0,%1,%2,%3}, {%4,%5,%6,%7}, {%8,%9}, {%0,%1,%2,%3};"
        : "+f"(d[0]), "+f"(d[1]), "+f"(d[2]), "+f"(d[3])
        : "r"(a[0]), "r"(a[1]), "r"(a[2]), "r"(a[3]), "r"(b[0]), "r"(b[1]));
}

#define MBAR_INIT(a, c) \
    asm volatile("mbarrier.init.shared.b64 [%0], %1;" :: "r"(a), "r"(c) : "memory")
#define MBAR_EXPECT(a, bytes) \
    asm volatile("mbarrier.arrive.expect_tx.shared.b64 _, [%0], %1;" \
                 :: "r"(a), "r"((uint32_t)(bytes)) : "memory")
#define CP_BULK(dst, src, bytes, mbar) \
    asm volatile("cp.async.bulk.shared::cta.global.mbarrier::complete_tx::bytes " \
                 "[%0], [%1], %2, [%3];" \
                 :: "r"(dst), "l"(src), "r"((uint32_t)(bytes)), "r"(mbar) : "memory")

__device__ __forceinline__ void mbar_wait(uint32_t mbar, int parity) {
    asm volatile(
        "{\n\t.reg .pred P;\n"
        "W%=:\n\t"
        "mbarrier.try_wait.parity.acquire.cta.shared::cta.b64 P, [%0], %1, 0x989680;\n\t"
        "@P bra D%=;\n\t"
        "bra W%=;\n"
        "D%=:\n\t}"
        :: "r"(mbar), "r"((uint32_t)parity) : "memory");
}

// ---------------------------------------------------------------------------
// Tensor GEMM (R13-measured config, unchanged):
// C[M,N] = (Ah+Al)[M,K] @ (Bh+Bl)[N,K]^T, 128x128 tile, BK=32, 256 thr,
// 2 CTAs/SM, cp.async.bulk chunk loads + mbarrier pipeline.
// MODE: bit0 +bias[n], bit1 +res[m,n], bit2 relu, bit3 write bf16 hi/lo split
// ---------------------------------------------------------------------------
#define TM 128
#define TN 128
#define BK 32
#define NTHR 256
#define SA 40
#define TILE_BYT 10240
#define STAGE_BYT (4*TILE_BYT)
#define GEMM_SMEM (2*STAGE_BYT + 64)

template<int MODE, bool SWAPG>
__global__ void __launch_bounds__(NTHR, 2) tc_gemm(
    int M, int N, int K,
    const __nv_bfloat16* __restrict__ Ah, const __nv_bfloat16* __restrict__ Al,
    const __nv_bfloat16* __restrict__ Bh, const __nv_bfloat16* __restrict__ Bl,
    const float* __restrict__ bias, const float* __restrict__ res,
    float* __restrict__ C, __nv_bfloat16* __restrict__ Ch,
    __nv_bfloat16* __restrict__ Cl)
{
    extern __shared__ __nv_bfloat16 sm[];
    uint32_t sbase = smem_u32(sm);
    uint32_t ctrl  = sbase + 2*STAGE_BYT;
    int tid = threadIdx.x;
    int bm = SWAPG ? blockIdx.x : blockIdx.y;
    int bn = SWAPG ? blockIdx.y : blockIdx.x;
    int warp = tid >> 5, lane = tid & 31;
    int wm = warp & 1, wn = warp >> 1;

    const int KC = K >> 5;
    const __nv_bfloat16* tAh = Ah + (size_t)bm * KC * 5120;
    const __nv_bfloat16* tAl = Al + (size_t)bm * KC * 5120;
    const __nv_bfloat16* tBh = Bh + (size_t)bn * KC * 5120;
    const __nv_bfloat16* tBl = Bl + (size_t)bn * KC * 5120;

    if (tid == 0) { MBAR_INIT(ctrl, 1); MBAR_INIT(ctrl + 8, 1); }
    __syncthreads();

    float acc[4][4][4];
    #pragma unroll
    for (int i = 0; i < 4; i++)
        #pragma unroll
        for (int j = 0; j < 4; j++)
            #pragma unroll
            for (int u = 0; u < 4; u++) acc[i][j][u] = 0.f;

    int mat = lane >> 3;
    int row_off = (mat & 1) * 8 + (lane & 7);
    int kblk_off = (mat >> 1) * 8;

    if (tid == 0) {
        MBAR_EXPECT(ctrl, STAGE_BYT);
        uint32_t sb = sbase;
        CP_BULK(sb,              (const void*)(tAh), TILE_BYT, ctrl);
        CP_BULK(sb +   TILE_BYT, (const void*)(tAl), TILE_BYT, ctrl);
        CP_BULK(sb + 2*TILE_BYT, (const void*)(tBh), TILE_BYT, ctrl);
        CP_BULK(sb + 3*TILE_BYT, (const void*)(tBl), TILE_BYT, ctrl);
    }

    int ph[2] = {0, 0};
    for (int c = 0; c < KC; c++) {
        int s = c & 1;
        if (c + 1 < KC && tid == 0) {
            uint32_t mb = ctrl + (uint32_t)((s ^ 1) * 8);
            MBAR_EXPECT(mb, STAGE_BYT);
            uint32_t sb = sbase + (uint32_t)((s ^ 1) * STAGE_BYT);
            size_t go = (size_t)(c + 1) * 5120;
            CP_BULK(sb,              (const void*)(tAh + go), TILE_BYT, mb);
            CP_BULK(sb +   TILE_BYT, (const void*)(tAl + go), TILE_BYT, mb);
            CP_BULK(sb + 2*TILE_BYT, (const void*)(tBh + go), TILE_BYT, mb);
            CP_BULK(sb + 3*TILE_BYT, (const void*)(tBl + go), TILE_BYT, mb);
        }
        mbar_wait(ctrl + (uint32_t)(s * 8), ph[s]);
        ph[s] ^= 1;

        uint32_t stg = sbase + (uint32_t)(s * STAGE_BYT);
        uint32_t Ash = stg, Asl = stg + TILE_BYT;
        uint32_t Bsh = stg + 2*TILE_BYT, Bsl = stg + 3*TILE_BYT;

        #pragma unroll
        for (int ks = 0; ks < 2; ks++) {
            int k0 = ks * 16 + kblk_off;
            uint32_t af[4][4], bf[2][4];
            // pass 0: Ah * Bh
            #pragma unroll
            for (int mt = 0; mt < 4; mt++) {
                int r = wm * 64 + mt * 16 + row_off;
                ldmat_x4(af[mt], Ash + (uint32_t)((r * SA + k0) * 2));
            }
            #pragma unroll
            for (int ng = 0; ng < 2; ng++) {
                int r = wn * 32 + ng * 16 + row_off;
                ldmat_x4(bf[ng], Bsh + (uint32_t)((r * SA + k0) * 2));
            }
            #pragma unroll
            for (int mt = 0; mt < 4; mt++)
                #pragma unroll
                for (int nt = 0; nt < 4; nt++) {
                    uint32_t bb[2] = { bf[nt >> 1][nt & 1],
                                       bf[nt >> 1][2 + (nt & 1)] };
                    mma16816(acc[mt][nt], af[mt], bb);
                }
            // pass 1: Ah * Bl (af stays live)
            #pragma unroll
            for (int ng = 0; ng < 2; ng++) {
                int r = wn * 32 + ng * 16 + row_off;
                ldmat_x4(bf[ng], Bsl + (uint32_t)((r * SA + k0) * 2));
            }
            #pragma unroll
            for (int mt = 0; mt < 4; mt++)
                #pragma unroll
                for (int nt = 0; nt < 4; nt++) {
                    uint32_t bb[2] = { bf[nt >> 1][nt & 1],
                                       bf[nt >> 1][2 + (nt & 1)] };
                    mma16816(acc[mt][nt], af[mt], bb);
                }
            // pass 2: Al * Bh
            #pragma unroll
            for (int mt = 0; mt < 4; mt++) {
                int r = wm * 64 + mt * 16 + row_off;
                ldmat_x4(af[mt], Asl + (uint32_t)((r * SA + k0) * 2));
            }
            #pragma unroll
            for (int ng = 0; ng < 2; ng++) {
                int r = wn * 32 + ng * 16 + row_off;
                ldmat_x4(bf[ng], Bsh + (uint32_t)((r * SA + k0) * 2));
            }
            #pragma unroll
            for (int mt = 0; mt < 4; mt++)
                #pragma unroll
                for (int nt = 0; nt < 4; nt++) {
                    uint32_t bb[2] = { bf[nt >> 1][nt & 1],
                                       bf[nt >> 1][2 + (nt & 1)] };
                    mma16816(acc[mt][nt], af[mt], bb);
                }
        }
        __syncthreads();
    }

    // epilogue (compile-time MODE)
    int qr = lane >> 2, qc = (lane & 3) * 2;
    #pragma unroll
    for (int mt = 0; mt < 4; mt++) {
        #pragma unroll
        for (int half = 0; half < 2; half++) {
            int grow = bm * TM + wm * 64 + mt * 16 + half * 8 + qr;
            size_t rowo = (size_t)grow * N;
            #pragma unroll
            for (int nt = 0; nt < 4; nt++) {
                int gcol = bn * TN + wn * 32 + nt * 8 + qc;
                float v0 = acc[mt][nt][half * 2 + 0];
                float v1 = acc[mt][nt][half * 2 + 1];
                if (MODE & 1) { v0 += bias[gcol]; v1 += bias[gcol + 1]; }
                if (MODE & 2) {
                    const float2 r2 = *(const float2*)(res + rowo + gcol);
                    v0 += r2.x; v1 += r2.y;
                }
                if (MODE & 4) { v0 = fmaxf(v0, 0.f); v1 = fmaxf(v1, 0.f); }
                if (MODE & 8) {
                    size_t o = tiled_off(grow, gcol, N >> 5);
                    __nv_bfloat16 h0 = __float2bfloat16(v0);
                    __nv_bfloat16 h1 = __float2bfloat16(v1);
                    __nv_bfloat162 hp; hp.x = h0; hp.y = h1;
                    __nv_bfloat162 lp;
                    lp.x = __float2bfloat16(v0 - __bfloat162float(h0));
                    lp.y = __float2bfloat16(v1 - __bfloat162float(h1));
                    *(__nv_bfloat162*)(Ch + o) = hp;
                    *(__nv_bfloat162*)(Cl + o) = lp;
                } else {
                    float2 o2; o2.x = v0; o2.y = v1;
                    *(float2*)(C + rowo + gcol) = o2;
                }
            }
        }
    }
}

// ---------------------------------------------------------------------------
// Weight transpose + split: W[K,N] fp32 -> tiled bf16 hi/lo images
// ---------------------------------------------------------------------------
__device__ __forceinline__ void tsplit_body(
    const float* __restrict__ W, __nv_bfloat16* __restrict__ Bh,
    __nv_bfloat16* __restrict__ Bl, int K, int N, float (*t)[33])
{
    int n0 = blockIdx.x * 32, k0 = blockIdx.y * 32;
    int tx = threadIdx.x & 31, ty = threadIdx.x >> 5;
    #pragma unroll
    for (int i = 0; i < 32; i += 8)
        t[ty + i][tx] = W[(size_t)(k0 + ty + i) * N + n0 + tx];
    __syncthreads();
    int kdiv32 = K >> 5;
    #pragma unroll
    for (int i = 0; i < 32; i += 8) {
        float v = t[tx][ty + i];
        __nv_bfloat16 hi = __float2bfloat16(v);
        size_t o = tiled_off(n0 + ty + i, k0 + tx, kdiv32);
        Bh[o] = hi;
        Bl[o] = __float2bfloat16(v - __bfloat162float(hi));
    }
}

__global__ __launch_bounds__(256) void transpose_split_kernel(
    const float* __restrict__ W, __nv_bfloat16* __restrict__ Bh,
    __nv_bfloat16* __restrict__ Bl, int K, int N)
{
    __shared__ float t[32][33];
    tsplit_body(W, Bh, Bl, K, N, t);
}

__global__ __launch_bounds__(256) void transpose_split_qkv_kernel(
    const float* __restrict__ Wq, const float* __restrict__ Wk,
    const float* __restrict__ Wv, __nv_bfloat16* __restrict__ Bh,
    __nv_bfloat16* __restrict__ Bl)
{
    __shared__ float t[32][33];
    int z = blockIdx.z;
    const float* W = (z == 0) ? Wq : (z == 1) ? Wk : Wv;
    size_t off = (size_t)z * (DD/128) * (DD/32) * 5120;
    tsplit_body(W, Bh + off, Bl + off, DD, DD, t);
}

// ---------------------------------------------------------------------------
// Embedding
// ---------------------------------------------------------------------------
__global__ __launch_bounds__(256) void embed_kernel(
    const int* __restrict__ ctx, const float* __restrict__ tok,
    const float* __restrict__ pos, float* __restrict__ x)
{
    int idx = blockIdx.x * 256 + threadIdx.x;
    int d  = idx & (DD - 1);
    int bt = idx >> 10;
    int t  = bt & (TT - 1);
    int v  = ctx[bt];
    x[idx] = tok[(size_t)v * DD + d] + pos[(size_t)t * DD + d];
}

// ---------------------------------------------------------------------------
// LayerNorm fused with tiled bf16 hi/lo split output
// ---------------------------------------------------------------------------
__global__ __launch_bounds__(256) void ln_split_kernel(
    const float* __restrict__ x, const float* __restrict__ s,
    const float* __restrict__ b, __nv_bfloat16* __restrict__ yh,
    __nv_bfloat16* __restrict__ yl)
{
    int row = blockIdx.x;
    const float* xr = x + (size_t)row * DD;
    int tid = threadIdx.x;

    float v0 = xr[tid], v1 = xr[tid+256], v2 = xr[tid+512], v3 = xr[tid+768];
    float sum = v0+v1+v2+v3;
    float sq  = v0*v0+v1*v1+v2*v2+v3*v3;
    #pragma unroll
    for (int o = 16; o > 0; o >>= 1) {
        sum += __shfl_xor_sync(0xFFFFFFFFu, sum, o);
        sq  += __shfl_xor_sync(0xFFFFFFFFu, sq,  o);
    }
    __shared__ float ssum[8], ssq[8], red[2];
    if ((tid & 31) == 0) { ssum[tid>>5] = sum; ssq[tid>>5] = sq; }
    __syncthreads();
    if (tid < 32) {
        float a = (tid < 8) ? ssum[tid] : 0.f;
        float c = (tid < 8) ? ssq[tid]  : 0.f;
        #pragma unroll
        for (int o = 4; o > 0; o >>= 1) {
            a += __shfl_xor_sync(0xFFFFFFFFu, a, o);
            c += __shfl_xor_sync(0xFFFFFFFFu, c, o);
        }
        if (tid == 0) { red[0] = a; red[1] = c; }
    }
    __syncthreads();
    float mean = red[0] * (1.f/DD);
    float var  = red[1] * (1.f/DD) - mean*mean;
    float inv  = rsqrtf(var + 1e-5f);
    #pragma unroll
    for (int i = 0; i < 4; i++) {
        int c = tid + i*256;
        float val = (xr[c] - mean) * inv * s[c] + b[c];
        __nv_bfloat16 hi = __float2bfloat16(val);
        size_t o = tiled_off(row, c, DD >> 5);
        yh[o] = hi;
        yl[o] = __float2bfloat16(val - __bfloat162float(hi));
    }
}

// ---------------------------------------------------------------------------
// Flash attention (causal), QKV packed [M,3072]; tiled bf16 hi/lo output.
// R14: 256 threads / block, TWO adjacent 128-row q-tiles share K/V smem tiles
// (halved K/V smem fill traffic, doubled warps/SM). Bit-exact vs R13:
// masked keys produce p=0 / corr=1 — identical arithmetic on live data.
// ---------------------------------------------------------------------------
__global__ __launch_bounds__(256) void attn_kernel(
    const float* __restrict__ QKV, __nv_bfloat16* __restrict__ Oh,
    __nv_bfloat16* __restrict__ Ol)
{
    int qt = blockIdx.x, h = blockIdx.y, b = blockIdx.z;
    int tid = threadIdx.x;
    int q_idx = qt * 256 + tid;

    const float* qp = QKV + ((size_t)(b*TT) + q_idx) * QKVD + h * HD;

    float qr[64];
    #pragma unroll
    for (int c = 0; c < 16; c++) {
        float4 t4 = *(const float4*)(qp + c*4);
        qr[4*c+0] = t4.x * 0.125f; qr[4*c+1] = t4.y * 0.125f;
        qr[4*c+2] = t4.z * 0.125f; qr[4*c+3] = t4.w * 0.125f;
    }
    float ob[64];
    #pragma unroll
    for (int d = 0; d < 64; d++) ob[d] = 0.f;
    float m = -1e30f, lsum = 0.f;

    __shared__ float4 Ks[16][16];
    __shared__ float4 Vs[16][16];

    int kend = qt * 256 + 256;
    for (int k0 = 0; k0 < kend; k0 += 16) {
        __syncthreads();
        {
            int r = tid >> 4, c = tid & 15;
            size_t rb = ((size_t)(b*TT) + k0 + r) * QKVD + h * HD + c*4;
            Ks[r][c] = *(const float4*)(QKV + rb + DD);
            Vs[r][c] = *(const float4*)(QKV + rb + 2*DD);
        }
        __syncthreads();

        float s[16];
        #pragma unroll
        for (int j = 0; j < 16; j++) {
            float acc = 0.f;
            #pragma unroll
            for (int c = 0; c < 16; c++) {
                float4 kk = Ks[j][c];
                acc += qr[4*c+0]*kk.x + qr[4*c+1]*kk.y
                     + qr[4*c+2]*kk.z + qr[4*c+3]*kk.w;
            }
            s[j] = (k0 + j <= q_idx) ? acc : -1e30f;
        }
        float mt = m;
        #pragma unroll
        for (int j = 0; j < 16; j++) mt = fmaxf(mt, s[j]);
        float corr = __expf(m - mt);
        m = mt;
        lsum *= corr;
        #pragma unroll
        for (int d = 0; d < 64; d++) ob[d] *= corr;

        #pragma unroll
        for (int j = 0; j < 16; j++) {
            float p = __expf(s[j] - m);
            lsum += p;
            #pragma unroll
            for (int c = 0; c < 16; c++) {
                float4 vv = Vs[j][c];
                ob[4*c+0] += p * vv.x; ob[4*c+1] += p * vv.y;
                ob[4*c+2] += p * vv.z; ob[4*c+3] += p * vv.w;
            }
        }
    }

    float inv = 1.f / lsum;
    int row = b*TT + q_idx;
    #pragma unroll
    for (int c = 0; c < 32; c++) {
        float u0 = ob[2*c+0]*inv, u1 = ob[2*c+1]*inv;
        int k = h * HD + 2*c;
        size_t o = tiled_off(row, k, DD >> 5);
        __nv_bfloat16 h0 = __float2bfloat16(u0);
        __nv_bfloat16 h1 = __float2bfloat16(u1);
        __nv_bfloat162 hp; hp.x = h0; hp.y = h1;
        __nv_bfloat162 lp;
        lp.x = __float2bfloat16(u0 - __bfloat162float(h0));
        lp.y = __float2bfloat16(u1 - __bfloat162float(h1));
        *(__nv_bfloat162*)(Oh + o) = hp;
        *(__nv_bfloat162*)(Ol + o) = lp;
    }
}

// ---------------------------------------------------------------------------
// Host orchestration
// ---------------------------------------------------------------------------
template<int MODE, bool SWAPG>
static void launch_gemm(const __nv_bfloat16* Ah, const __nv_bfloat16* Al,
                        const __nv_bfloat16* Bh, const __nv_bfloat16* Bl,
                        const float* bias, const float* res, float* C,
                        __nv_bfloat16* Ch, __nv_bfloat16* Cl,
                        int M, int N, int K)
{
    dim3 grid = SWAPG ? dim3(M / TM, N / TN) : dim3(N / TN, M / TM);
    tc_gemm<MODE, SWAPG><<<grid, NTHR, GEMM_SMEM>>>(M, N, K, Ah, Al, Bh, Bl,
                                                    bias, res, C, Ch, Cl);
}

static void launch_tsplit(const float* W, __nv_bfloat16* Bh, __nv_bfloat16* Bl,
                          int K, int N)
{
    dim3 grid(N / 32, K / 32);
    transpose_split_kernel<<<grid, 256>>>(W, Bh, Bl, K, N);
}

extern "C" void kernel_launch(void* const* d_in, const int* in_sizes, int n_in,
                              void* d_out, int out_size)
{
    const int*   ctx  = (const int*)  d_in[0];
    const float* tok  = (const float*)d_in[1];
    const float* pos  = (const float*)d_in[2];
    const float* Wq   = (const float*)d_in[3];
    const float* Wk   = (const float*)d_in[4];
    const float* Wv   = (const float*)d_in[5];
    const float* Wo   = (const float*)d_in[6];
    const float* bo   = (const float*)d_in[7];
    const float* ln1s = (const float*)d_in[8];
    const float* ln1b = (const float*)d_in[9];
    const float* W1   = (const float*)d_in[10];
    const float* b1   = (const float*)d_in[11];
    const float* W2   = (const float*)d_in[12];
    const float* b2   = (const float*)d_in[13];
    const float* ln2s = (const float*)d_in[14];
    const float* ln2b = (const float*)d_in[15];
    const float* lnfs = (const float*)d_in[16];
    const float* lnfb = (const float*)d_in[17];
    const float* Wout = (const float*)d_in[18];
    const float* bout = (const float*)d_in[19];
    float* out = (float*)d_out;

    cudaFuncSetAttribute(tc_gemm<0,false>,  cudaFuncAttributeMaxDynamicSharedMemorySize, GEMM_SMEM);
    cudaFuncSetAttribute(tc_gemm<3,false>,  cudaFuncAttributeMaxDynamicSharedMemorySize, GEMM_SMEM);
    cudaFuncSetAttribute(tc_gemm<13,false>, cudaFuncAttributeMaxDynamicSharedMemorySize, GEMM_SMEM);
    cudaFuncSetAttribute(tc_gemm<1,true>,   cudaFuncAttributeMaxDynamicSharedMemorySize, GEMM_SMEM);

    float *x, *qkv;
    __nv_bfloat16 *ah, *al, *fh, *fl;
    __nv_bfloat16 *wqkvh, *wqkvl, *woh, *wol, *w1h, *w1l, *w2h, *w2l, *wouth, *woutl;
    cudaGetSymbolAddress((void**)&x,    g_x);
    cudaGetSymbolAddress((void**)&qkv,  g_qkv);
    cudaGetSymbolAddress((void**)&ah,   g_ah);
    cudaGetSymbolAddress((void**)&al,   g_al);
    cudaGetSymbolAddress((void**)&fh,   g_fh);
    cudaGetSymbolAddress((void**)&fl,   g_fl);
    cudaGetSymbolAddress((void**)&wqkvh,g_wqkvh);
    cudaGetSymbolAddress((void**)&wqkvl,g_wqkvl);
    cudaGetSymbolAddress((void**)&woh,  g_woh);
    cudaGetSymbolAddress((void**)&wol,  g_wol);
    cudaGetSymbolAddress((void**)&w1h,  g_w1h);
    cudaGetSymbolAddress((void**)&w1l,  g_w1l);
    cudaGetSymbolAddress((void**)&w2h,  g_w2h);
    cudaGetSymbolAddress((void**)&w2l,  g_w2l);
    cudaGetSymbolAddress((void**)&wouth,g_wouth);
    cudaGetSymbolAddress((void**)&woutl,g_woutl);

    const size_t WQKV_L = (size_t)(QKVD/128)*(DD/32)*5120;
    const size_t WDD_L  = (size_t)(DD/128)*(DD/32)*5120;
    const size_t W1_L   = (size_t)(DFF/128)*(DD/32)*5120;
    const size_t W2_L   = (size_t)(DD/128)*(DFF/32)*5120;

    // Stream index 0: fused layer-0 QKV weight prep
    {
        dim3 grid(DD / 32, DD / 32, 3);
        transpose_split_qkv_kernel<<<grid, 256>>>(Wq, Wk, Wv, wqkvh, wqkvl);
    }
    // Index 1: embedding
    embed_kernel<<<(MM*DD)/256, 256>>>(ctx, tok, pos, x);
    // Index 2: LN1 (layer 0)
    ln_split_kernel<<<MM, 256>>>(x, ln1s, ln1b, ah, al);
    // Index 3: layer-0 QKV GEMM  (-> ncu global index 5)
    launch_gemm<0, false>(ah, al, wqkvh, wqkvl, nullptr, nullptr, qkv,
                          nullptr, nullptr, MM, QKVD, DD);

    // Remaining weight prep
    for (int l = 0; l < LL; l++) {
        if (l > 0) {
            dim3 grid(DD / 32, DD / 32, 3);
            transpose_split_qkv_kernel<<<grid, 256>>>(
                Wq + (size_t)l*DD*DD, Wk + (size_t)l*DD*DD, Wv + (size_t)l*DD*DD,
                wqkvh + (size_t)l*WQKV_L, wqkvl + (size_t)l*WQKV_L);
        }
        launch_tsplit(Wo + (size_t)l*DD*DD,  woh + (size_t)l*WDD_L, wol + (size_t)l*WDD_L, DD, DD);
        launch_tsplit(W1 + (size_t)l*DD*DFF, w1h + (size_t)l*W1_L,  w1l + (size_t)l*W1_L,  DD, DFF);
        launch_tsplit(W2 + (size_t)l*DFF*DD, w2h + (size_t)l*W2_L,  w2l + (size_t)l*W2_L,  DFF, DD);
    }
    launch_tsplit(Wout, wouth, woutl, DD, VV);

    for (int l = 0; l < LL; l++) {
        const __nv_bfloat16* lwqh = wqkvh + (size_t)l*WQKV_L;
        const __nv_bfloat16* lwql = wqkvl + (size_t)l*WQKV_L;
        const __nv_bfloat16* lwoh = woh + (size_t)l*WDD_L;
        const __nv_bfloat16* lwol = wol + (size_t)l*WDD_L;
        const __nv_bfloat16* lw1h = w1h + (size_t)l*W1_L;
        const __nv_bfloat16* lw1l = w1l + (size_t)l*W1_L;
        const __nv_bfloat16* lw2h = w2h + (size_t)l*W2_L;
        const __nv_bfloat16* lw2l = w2l + (size_t)l*W2_L;

        if (l > 0) {
            ln_split_kernel<<<MM, 256>>>(x, ln1s + l*DD, ln1b + l*DD, ah, al);
            launch_gemm<0, false>(ah, al, lwqh, lwql, nullptr, nullptr, qkv,
                                  nullptr, nullptr, MM, QKVD, DD);
        }

        // attention -> ah/al (tiled bf16 split); 2 q-tiles per block
        {
            dim3 grid(TT/256, HH, BB);
            attn_kernel<<<grid, 256>>>(qkv, ah, al);
        }

        // x = x + att @ Wo + bo
        launch_gemm<3, false>(ah, al, lwoh, lwol, bo + l*DD, x, x,
                              nullptr, nullptr, MM, DD, DD);

        // ah/al = split(LN2(x)); fh/fl = split(relu(ah @ W1 + b1))
        ln_split_kernel<<<MM, 256>>>(x, ln2s + l*DD, ln2b + l*DD, ah, al);
        launch_gemm<13, false>(ah, al, lw1h, lw1l, b1 + l*DFF, nullptr, nullptr,
                               fh, fl, MM, DFF, DD);

        // x = x + fh @ W2 + b2
        launch_gemm<3, false>(fh, fl, lw2h, lw2l, b2 + l*DD, x, x,
                              nullptr, nullptr, MM, DD, DFF);
    }

    // final LN + logits (M-fast rasterization: stream 131MB B once)
    ln_split_kernel<<<MM, 256>>>(x, lnfs, lnfb, ah, al);
    launch_gemm<1, true>(ah, al, wouth, woutl, bout, nullptr, out,
                         nullptr, nullptr, MM, VV, DD);
}

// round 16
// speedup vs baseline: 1.6629x; 1.6629x over previous
#include <cuda_runtime.h>
#include <cuda_bf16.h>
#include <math.h>
#include <stdint.h>

// Problem constants
#define BB   2
#define TT   2048
#define DD   1024
#define LL   4
#define HH   16
#define HD   64
#define VV   32000
#define DFF  4096
#define MM   (BB*TT)        // 4096 rows
#define QKVD 3072
#define KVP  72             // padded hd stride for K/V split buffers

// ---------------------------------------------------------------------------
// Scratch (device globals; allocation is forbidden). 256B aligned for bulk.
// Tiled bf16 layout for GEMM operands: [row/128][k/32] tiles of 128x40 elems
// (32 data + 8 pad) = 5120 elems = 10240 B contiguous == the smem image.
// ---------------------------------------------------------------------------
__device__ __align__(256) float g_x  [MM*DD];
__device__ __align__(256) float g_qkv[MM*QKVD];

__device__ __align__(256) __nv_bfloat16 g_ah[(MM/128)*(DD/32)*5120],  g_al[(MM/128)*(DD/32)*5120];
__device__ __align__(256) __nv_bfloat16 g_fh[(MM/128)*(DFF/32)*5120], g_fl[(MM/128)*(DFF/32)*5120];

__device__ __align__(256) __nv_bfloat16 g_wqkvh[(QKVD/128)*(DD/32)*5120*LL], g_wqkvl[(QKVD/128)*(DD/32)*5120*LL];
__device__ __align__(256) __nv_bfloat16 g_woh  [(DD/128)*(DD/32)*5120*LL],   g_wol  [(DD/128)*(DD/32)*5120*LL];
__device__ __align__(256) __nv_bfloat16 g_w1h  [(DFF/128)*(DD/32)*5120*LL],  g_w1l  [(DFF/128)*(DD/32)*5120*LL];
__device__ __align__(256) __nv_bfloat16 g_w2h  [(DD/128)*(DFF/32)*5120*LL],  g_w2l  [(DD/128)*(DFF/32)*5120*LL];
__device__ __align__(256) __nv_bfloat16 g_wouth[(VV/128)*(DD/32)*5120],      g_woutl[(VV/128)*(DD/32)*5120];

// K/V bf16 hi/lo split, layout [b*HH+h][key][KVP]
__device__ __align__(256) __nv_bfloat16 g_kh[BB*HH*TT*KVP], g_kl[BB*HH*TT*KVP];
__device__ __align__(256) __nv_bfloat16 g_vh[BB*HH*TT*KVP], g_vl[BB*HH*TT*KVP];

// tiled offset: element index for (row, k) with K/32 chunks per row-tile
__device__ __forceinline__ size_t tiled_off(int row, int k, int kdiv32) {
    return ((size_t)(row >> 7) * kdiv32 + (k >> 5)) * 5120
         + (size_t)((row & 127) * 40 + (k & 31));
}

// ---------------------------------------------------------------------------
// PTX helpers (sm_90 base ISA; no 'a'-suffix features)
// ---------------------------------------------------------------------------
__device__ __forceinline__ uint32_t smem_u32(const void* p) {
    return (uint32_t)__cvta_generic_to_shared(p);
}
#define CP_ASYNC16(dst, src) \
    asm volatile("cp.async.cg.shared.global [%0], [%1], 16;" :: "r"(dst), "l"(src))
#define CP_COMMIT() asm volatile("cp.async.commit_group;" ::: "memory")
#define CP_WAIT0()  asm volatile("cp.async.wait_group 0;" ::: "memory")

__device__ __forceinline__ void ldmat_x4(uint32_t* r, uint32_t addr) {
    asm volatile("ldmatrix.sync.aligned.m8n8.x4.shared.b16 {%0,%1,%2,%3}, [%4];"
                 : "=r"(r[0]), "=r"(r[1]), "=r"(r[2]), "=r"(r[3]) : "r"(addr));
}
__device__ __forceinline__ void ldmat_x4t(uint32_t* r, uint32_t addr) {
    asm volatile("ldmatrix.sync.aligned.m8n8.x4.trans.shared.b16 {%0,%1,%2,%3}, [%4];"
                 : "=r"(r[0]), "=r"(r[1]), "=r"(r[2]), "=r"(r[3]) : "r"(addr));
}
__device__ __forceinline__ void mma16816(float* d, const uint32_t* a,
                                         const uint32_t* b) {
    asm volatile(
        "mma.sync.aligned.m16n8k16.row.col.f32.bf16.bf16.f32 "
        "{%0,%1,%2,%3}, {%4,%5,%6,%7}, {%8,%9}, {%0,%1,%2,%3};"
        : "+f"(d[0]), "+f"(d[1]), "+f"(d[2]), "+f"(d[3])
        : "r"(a[0]), "r"(a[1]), "r"(a[2]), "r"(a[3]), "r"(b[0]), "r"(b[1]));
}

#define MBAR_INIT(a, c) \
    asm volatile("mbarrier.init.shared.b64 [%0], %1;" :: "r"(a), "r"(c) : "memory")
#define MBAR_EXPECT(a, bytes) \
    asm volatile("mbarrier.arrive.expect_tx.shared.b64 _, [%0], %1;" \
                 :: "r"(a), "r"((uint32_t)(bytes)) : "memory")
#define CP_BULK(dst, src, bytes, mbar) \
    asm volatile("cp.async.bulk.shared::cta.global.mbarrier::complete_tx::bytes " \
                 "[%0], [%1], %2, [%3];" \
                 :: "r"(dst), "l"(src), "r"((uint32_t)(bytes)), "r"(mbar) : "memory")

__device__ __forceinline__ void mbar_wait(uint32_t mbar, int parity) {
    asm volatile(
        "{\n\t.reg .pred P;\n"
        "W%=:\n\t"
        "mbarrier.try_wait.parity.acquire.cta.shared::cta.b64 P, [%0], %1, 0x989680;\n\t"
        "@P bra D%=;\n\t"
        "bra W%=;\n"
        "D%=:\n\t}"
        :: "r"(mbar), "r"((uint32_t)parity) : "memory");
}

// split two floats into bf16 hi-pair and lo-pair (packed u32)
__device__ __forceinline__ void split2(float a, float b, uint32_t& hi, uint32_t& lo) {
    __nv_bfloat16 ha = __float2bfloat16(a), hb = __float2bfloat16(b);
    __nv_bfloat162 hp; hp.x = ha; hp.y = hb;
    __nv_bfloat162 lp;
    lp.x = __float2bfloat16(a - __bfloat162float(ha));
    lp.y = __float2bfloat16(b - __bfloat162float(hb));
    hi = *(uint32_t*)&hp; lo = *(uint32_t*)&lp;
}

// ---------------------------------------------------------------------------
// Tensor GEMM (R13-measured config, unchanged)
// ---------------------------------------------------------------------------
#define TM 128
#define TN 128
#define BK 32
#define NTHR 256
#define SA 40
#define TILE_BYT 10240
#define STAGE_BYT (4*TILE_BYT)
#define GEMM_SMEM (2*STAGE_BYT + 64)

template<int MODE, bool SWAPG>
__global__ void __launch_bounds__(NTHR, 2) tc_gemm(
    int M, int N, int K,
    const __nv_bfloat16* __restrict__ Ah, const __nv_bfloat16* __restrict__ Al,
    const __nv_bfloat16* __restrict__ Bh, const __nv_bfloat16* __restrict__ Bl,
    const float* __restrict__ bias, const float* __restrict__ res,
    float* __restrict__ C, __nv_bfloat16* __restrict__ Ch,
    __nv_bfloat16* __restrict__ Cl)
{
    extern __shared__ __nv_bfloat16 sm[];
    uint32_t sbase = smem_u32(sm);
    uint32_t ctrl  = sbase + 2*STAGE_BYT;
    int tid = threadIdx.x;
    int bm = SWAPG ? blockIdx.x : blockIdx.y;
    int bn = SWAPG ? blockIdx.y : blockIdx.x;
    int warp = tid >> 5, lane = tid & 31;
    int wm = warp & 1, wn = warp >> 1;

    const int KC = K >> 5;
    const __nv_bfloat16* tAh = Ah + (size_t)bm * KC * 5120;
    const __nv_bfloat16* tAl = Al + (size_t)bm * KC * 5120;
    const __nv_bfloat16* tBh = Bh + (size_t)bn * KC * 5120;
    const __nv_bfloat16* tBl = Bl + (size_t)bn * KC * 5120;

    if (tid == 0) { MBAR_INIT(ctrl, 1); MBAR_INIT(ctrl + 8, 1); }
    __syncthreads();

    float acc[4][4][4];
    #pragma unroll
    for (int i = 0; i < 4; i++)
        #pragma unroll
        for (int j = 0; j < 4; j++)
            #pragma unroll
            for (int u = 0; u < 4; u++) acc[i][j][u] = 0.f;

    int mat = lane >> 3;
    int row_off = (mat & 1) * 8 + (lane & 7);
    int kblk_off = (mat >> 1) * 8;

    if (tid == 0) {
        MBAR_EXPECT(ctrl, STAGE_BYT);
        uint32_t sb = sbase;
        CP_BULK(sb,              (const void*)(tAh), TILE_BYT, ctrl);
        CP_BULK(sb +   TILE_BYT, (const void*)(tAl), TILE_BYT, ctrl);
        CP_BULK(sb + 2*TILE_BYT, (const void*)(tBh), TILE_BYT, ctrl);
        CP_BULK(sb + 3*TILE_BYT, (const void*)(tBl), TILE_BYT, ctrl);
    }

    int ph[2] = {0, 0};
    for (int c = 0; c < KC; c++) {
        int s = c & 1;
        if (c + 1 < KC && tid == 0) {
            uint32_t mb = ctrl + (uint32_t)((s ^ 1) * 8);
            MBAR_EXPECT(mb, STAGE_BYT);
            uint32_t sb = sbase + (uint32_t)((s ^ 1) * STAGE_BYT);
            size_t go = (size_t)(c + 1) * 5120;
            CP_BULK(sb,              (const void*)(tAh + go), TILE_BYT, mb);
            CP_BULK(sb +   TILE_BYT, (const void*)(tAl + go), TILE_BYT, mb);
            CP_BULK(sb + 2*TILE_BYT, (const void*)(tBh + go), TILE_BYT, mb);
            CP_BULK(sb + 3*TILE_BYT, (const void*)(tBl + go), TILE_BYT, mb);
        }
        mbar_wait(ctrl + (uint32_t)(s * 8), ph[s]);
        ph[s] ^= 1;

        uint32_t stg = sbase + (uint32_t)(s * STAGE_BYT);
        uint32_t Ash = stg, Asl = stg + TILE_BYT;
        uint32_t Bsh = stg + 2*TILE_BYT, Bsl = stg + 3*TILE_BYT;

        #pragma unroll
        for (int ks = 0; ks < 2; ks++) {
            int k0 = ks * 16 + kblk_off;
            uint32_t af[4][4], bf[2][4];
            #pragma unroll
            for (int mt = 0; mt < 4; mt++) {
                int r = wm * 64 + mt * 16 + row_off;
                ldmat_x4(af[mt], Ash + (uint32_t)((r * SA + k0) * 2));
            }
            #pragma unroll
            for (int ng = 0; ng < 2; ng++) {
                int r = wn * 32 + ng * 16 + row_off;
                ldmat_x4(bf[ng], Bsh + (uint32_t)((r * SA + k0) * 2));
            }
            #pragma unroll
            for (int mt = 0; mt < 4; mt++)
                #pragma unroll
                for (int nt = 0; nt < 4; nt++) {
                    uint32_t bb[2] = { bf[nt >> 1][nt & 1],
                                       bf[nt >> 1][2 + (nt & 1)] };
                    mma16816(acc[mt][nt], af[mt], bb);
                }
            #pragma unroll
            for (int ng = 0; ng < 2; ng++) {
                int r = wn * 32 + ng * 16 + row_off;
                ldmat_x4(bf[ng], Bsl + (uint32_t)((r * SA + k0) * 2));
            }
            #pragma unroll
            for (int mt = 0; mt < 4; mt++)
                #pragma unroll
                for (int nt = 0; nt < 4; nt++) {
                    uint32_t bb[2] = { bf[nt >> 1][nt & 1],
                                       bf[nt >> 1][2 + (nt & 1)] };
                    mma16816(acc[mt][nt], af[mt], bb);
                }
            #pragma unroll
            for (int mt = 0; mt < 4; mt++) {
                int r = wm * 64 + mt * 16 + row_off;
                ldmat_x4(af[mt], Asl + (uint32_t)((r * SA + k0) * 2));
            }
            #pragma unroll
            for (int ng = 0; ng < 2; ng++) {
                int r = wn * 32 + ng * 16 + row_off;
                ldmat_x4(bf[ng], Bsh + (uint32_t)((r * SA + k0) * 2));
            }
            #pragma unroll
            for (int mt = 0; mt < 4; mt++)
                #pragma unroll
                for (int nt = 0; nt < 4; nt++) {
                    uint32_t bb[2] = { bf[nt >> 1][nt & 1],
                                       bf[nt >> 1][2 + (nt & 1)] };
                    mma16816(acc[mt][nt], af[mt], bb);
                }
        }
        __syncthreads();
    }

    int qr = lane >> 2, qc = (lane & 3) * 2;
    #pragma unroll
    for (int mt = 0; mt < 4; mt++) {
        #pragma unroll
        for (int half = 0; half < 2; half++) {
            int grow = bm * TM + wm * 64 + mt * 16 + half * 8 + qr;
            size_t rowo = (size_t)grow * N;
            #pragma unroll
            for (int nt = 0; nt < 4; nt++) {
                int gcol = bn * TN + wn * 32 + nt * 8 + qc;
                float v0 = acc[mt][nt][half * 2 + 0];
                float v1 = acc[mt][nt][half * 2 + 1];
                if (MODE & 1) { v0 += bias[gcol]; v1 += bias[gcol + 1]; }
                if (MODE & 2) {
                    const float2 r2 = *(const float2*)(res + rowo + gcol);
                    v0 += r2.x; v1 += r2.y;
                }
                if (MODE & 4) { v0 = fmaxf(v0, 0.f); v1 = fmaxf(v1, 0.f); }
                if (MODE & 8) {
                    size_t o = tiled_off(grow, gcol, N >> 5);
                    uint32_t hi, lo;
                    split2(v0, v1, hi, lo);
                    *(uint32_t*)(Ch + o) = hi;
                    *(uint32_t*)(Cl + o) = lo;
                } else {
                    float2 o2; o2.x = v0; o2.y = v1;
                    *(float2*)(C + rowo + gcol) = o2;
                }
            }
        }
    }
}

// ---------------------------------------------------------------------------
// Weight transpose + split (unchanged)
// ---------------------------------------------------------------------------
__device__ __forceinline__ void tsplit_body(
    const float* __restrict__ W, __nv_bfloat16* __restrict__ Bh,
    __nv_bfloat16* __restrict__ Bl, int K, int N, float (*t)[33])
{
    int n0 = blockIdx.x * 32, k0 = blockIdx.y * 32;
    int tx = threadIdx.x & 31, ty = threadIdx.x >> 5;
    #pragma unroll
    for (int i = 0; i < 32; i += 8)
        t[ty + i][tx] = W[(size_t)(k0 + ty + i) * N + n0 + tx];
    __syncthreads();
    int kdiv32 = K >> 5;
    #pragma unroll
    for (int i = 0; i < 32; i += 8) {
        float v = t[tx][ty + i];
        __nv_bfloat16 hi = __float2bfloat16(v);
        size_t o = tiled_off(n0 + ty + i, k0 + tx, kdiv32);
        Bh[o] = hi;
        Bl[o] = __float2bfloat16(v - __bfloat162float(hi));
    }
}

__global__ __launch_bounds__(256) void transpose_split_kernel(
    const float* __restrict__ W, __nv_bfloat16* __restrict__ Bh,
    __nv_bfloat16* __restrict__ Bl, int K, int N)
{
    __shared__ float t[32][33];
    tsplit_body(W, Bh, Bl, K, N, t);
}

__global__ __launch_bounds__(256) void transpose_split_qkv_kernel(
    const float* __restrict__ Wq, const float* __restrict__ Wk,
    const float* __restrict__ Wv, __nv_bfloat16* __restrict__ Bh,
    __nv_bfloat16* __restrict__ Bl)
{
    __shared__ float t[32][33];
    int z = blockIdx.z;
    const float* W = (z == 0) ? Wq : (z == 1) ? Wk : Wv;
    size_t off = (size_t)z * (DD/128) * (DD/32) * 5120;
    tsplit_body(W, Bh + off, Bl + off, DD, DD, t);
}

// ---------------------------------------------------------------------------
// Embedding / LayerNorm (unchanged)
// ---------------------------------------------------------------------------
__global__ __launch_bounds__(256) void embed_kernel(
    const int* __restrict__ ctx, const float* __restrict__ tok,
    const float* __restrict__ pos, float* __restrict__ x)
{
    int idx = blockIdx.x * 256 + threadIdx.x;
    int d  = idx & (DD - 1);
    int bt = idx >> 10;
    int t  = bt & (TT - 1);
    int v  = ctx[bt];
    x[idx] = tok[(size_t)v * DD + d] + pos[(size_t)t * DD + d];
}

__global__ __launch_bounds__(256) void ln_split_kernel(
    const float* __restrict__ x, const float* __restrict__ s,
    const float* __restrict__ b, __nv_bfloat16* __restrict__ yh,
    __nv_bfloat16* __restrict__ yl)
{
    int row = blockIdx.x;
    const float* xr = x + (size_t)row * DD;
    int tid = threadIdx.x;

    float v0 = xr[tid], v1 = xr[tid+256], v2 = xr[tid+512], v3 = xr[tid+768];
    float sum = v0+v1+v2+v3;
    float sq  = v0*v0+v1*v1+v2*v2+v3*v3;
    #pragma unroll
    for (int o = 16; o > 0; o >>= 1) {
        sum += __shfl_xor_sync(0xFFFFFFFFu, sum, o);
        sq  += __shfl_xor_sync(0xFFFFFFFFu, sq,  o);
    }
    __shared__ float ssum[8], ssq[8], red[2];
    if ((tid & 31) == 0) { ssum[tid>>5] = sum; ssq[tid>>5] = sq; }
    __syncthreads();
    if (tid < 32) {
        float a = (tid < 8) ? ssum[tid] : 0.f;
        float c = (tid < 8) ? ssq[tid]  : 0.f;
        #pragma unroll
        for (int o = 4; o > 0; o >>= 1) {
            a += __shfl_xor_sync(0xFFFFFFFFu, a, o);
            c += __shfl_xor_sync(0xFFFFFFFFu, c, o);
        }
        if (tid == 0) { red[0] = a; red[1] = c; }
    }
    __syncthreads();
    float mean = red[0] * (1.f/DD);
    float var  = red[1] * (1.f/DD) - mean*mean;
    float inv  = rsqrtf(var + 1e-5f);
    #pragma unroll
    for (int i = 0; i < 4; i++) {
        int c = tid + i*256;
        float val = (xr[c] - mean) * inv * s[c] + b[c];
        __nv_bfloat16 hi = __float2bfloat16(val);
        size_t o = tiled_off(row, c, DD >> 5);
        yh[o] = hi;
        yl[o] = __float2bfloat16(val - __bfloat162float(hi));
    }
}

// ---------------------------------------------------------------------------
// K/V pre-split: g_qkv fp32 -> g_k{h,l}/g_v{h,l} bf16, [b*HH+h][key][KVP]
// ---------------------------------------------------------------------------
__global__ __launch_bounds__(256) void kv_split_kernel(const float* __restrict__ QKV)
{
    int h = blockIdx.y, b = blockIdx.z;
    int key = blockIdx.x * 128 + (threadIdx.x >> 1);
    int half = threadIdx.x & 1;
    const float* src = QKV + ((size_t)(b*TT) + key) * QKVD + h * HD + half * 32;
    size_t dst = ((size_t)(b*HH + h) * TT + key) * KVP + half * 32;
    #pragma unroll
    for (int i = 0; i < 16; i++) {
        float2 k2 = *(const float2*)(src + DD + i*2);
        uint32_t hi, lo;
        split2(k2.x, k2.y, hi, lo);
        *(uint32_t*)(g_kh + dst + i*2) = hi;
        *(uint32_t*)(g_kl + dst + i*2) = lo;
        float2 v2 = *(const float2*)(src + 2*DD + i*2);
        split2(v2.x, v2.y, hi, lo);
        *(uint32_t*)(g_vh + dst + i*2) = hi;
        *(uint32_t*)(g_vl + dst + i*2) = lo;
    }
}

// ---------------------------------------------------------------------------
// Tensor-core flash attention (causal). Grid (T/64, H, B), 128 threads.
// 64 q-rows/block, 4 warps (16 q-rows each), 64-key chunks.
// 3xBF16 split for QK and PV; fp32 softmax state in registers.
// Output: tiled bf16 hi/lo (A-side image for the Wo GEMM).
// ---------------------------------------------------------------------------
__global__ void __launch_bounds__(128) attn_tc_kernel(
    const float* __restrict__ QKV, __nv_bfloat16* __restrict__ Oh,
    __nv_bfloat16* __restrict__ Ol)
{
    __shared__ __nv_bfloat16 sKh[64*KVP], sKl[64*KVP];
    __shared__ __nv_bfloat16 sVh[64*KVP], sVl[64*KVP];

    int qt = blockIdx.x, h = blockIdx.y, b = blockIdx.z;
    int tid = threadIdx.x, warp = tid >> 5, lane = tid & 31;
    int qbase = qt * 64;
    int bh = b * HH + h;

    uint32_t sKh_u = smem_u32(sKh), sKl_u = smem_u32(sKl);
    uint32_t sVh_u = smem_u32(sVh), sVl_u = smem_u32(sVl);

    // stage scaled Q into sKh/sKl (scale 1/8 is exact in bf16 split)
    {
        int row = tid >> 1, half = tid & 1;
        const float* qp = QKV + ((size_t)(b*TT) + qbase + row) * QKVD + h * HD + half * 32;
        __nv_bfloat16* dh = sKh + row * KVP + half * 32;
        __nv_bfloat16* dl = sKl + row * KVP + half * 32;
        #pragma unroll
        for (int i = 0; i < 16; i++) {
            float2 v = *(const float2*)(qp + i*2);
            uint32_t hi, lo;
            split2(v.x * 0.125f, v.y * 0.125f, hi, lo);
            *(uint32_t*)(dh + i*2) = hi;
            *(uint32_t*)(dl + i*2) = lo;
        }
    }
    __syncthreads();

    int mat = lane >> 3;
    int row_off = (mat & 1) * 8 + (lane & 7);
    int kblk = (mat >> 1) * 8;

    // Q fragments persist in registers (rows = warp*16 + frag rows)
    uint32_t qh[4][4], ql[4][4];
    #pragma unroll
    for (int kt = 0; kt < 4; kt++) {
        int r = warp * 16 + row_off;
        ldmat_x4(qh[kt], sKh_u + (uint32_t)((r * KVP + kt*16 + kblk) * 2));
        ldmat_x4(ql[kt], sKl_u + (uint32_t)((r * KVP + kt*16 + kblk) * 2));
    }
    __syncthreads();

    float o[8][4];
    #pragma unroll
    for (int j = 0; j < 8; j++)
        #pragma unroll
        for (int u = 0; u < 4; u++) o[j][u] = 0.f;
    float m0 = -1e30f, m1 = -1e30f, l0 = 0.f, l1 = 0.f;

    for (int kb = 0; kb <= qbase; kb += 64) {
        __syncthreads();   // previous chunk fully consumed
        // load K/V 64-key chunk (bf16 split, pre-converted)
        {
            size_t base = ((size_t)bh * TT + kb) * KVP;
            #pragma unroll
            for (int i = 0; i < 4; i++) {
                int idx = i * 128 + tid;           // 0..511
                int r = idx >> 3, g = idx & 7;
                uint32_t soff = (uint32_t)((r * KVP + g * 8) * 2);
                size_t goff = base + (size_t)r * KVP + g * 8;
                CP_ASYNC16(sKh_u + soff, (const void*)(g_kh + goff));
                CP_ASYNC16(sKl_u + soff, (const void*)(g_kl + goff));
                CP_ASYNC16(sVh_u + soff, (const void*)(g_vh + goff));
                CP_ASYNC16(sVl_u + soff, (const void*)(g_vl + goff));
            }
            CP_COMMIT(); CP_WAIT0();
        }
        __syncthreads();

        // S = Q K^T  (3 split passes), s[n8 tile j][4]
        float s[8][4];
        #pragma unroll
        for (int j = 0; j < 8; j++)
            #pragma unroll
            for (int u = 0; u < 4; u++) s[j][u] = 0.f;

        #pragma unroll
        for (int kt = 0; kt < 4; kt++) {
            uint32_t kf[4][4], kg[4][4];
            #pragma unroll
            for (int ng = 0; ng < 4; ng++) {
                int r = ng * 16 + row_off;
                ldmat_x4(kf[ng], sKh_u + (uint32_t)((r * KVP + kt*16 + kblk) * 2));
            }
            #pragma unroll
            for (int ng = 0; ng < 4; ng++) {
                uint32_t b0[2] = { kf[ng][0], kf[ng][2] };
                uint32_t b1[2] = { kf[ng][1], kf[ng][3] };
                mma16816(s[2*ng],   qh[kt], b0);
                mma16816(s[2*ng+1], qh[kt], b1);
            }
            #pragma unroll
            for (int ng = 0; ng < 4; ng++) {
                int r = ng * 16 + row_off;
                ldmat_x4(kg[ng], sKl_u + (uint32_t)((r * KVP + kt*16 + kblk) * 2));
            }
            #pragma unroll
            for (int ng = 0; ng < 4; ng++) {
                uint32_t b0[2] = { kg[ng][0], kg[ng][2] };
                uint32_t b1[2] = { kg[ng][1], kg[ng][3] };
                mma16816(s[2*ng],   qh[kt], b0);
                mma16816(s[2*ng+1], qh[kt], b1);
            }
            #pragma unroll
            for (int ng = 0; ng < 4; ng++) {
                uint32_t b0[2] = { kf[ng][0], kf[ng][2] };
                uint32_t b1[2] = { kf[ng][1], kf[ng][3] };
                mma16816(s[2*ng],   ql[kt], b0);
                mma16816(s[2*ng+1], ql[kt], b1);
            }
        }

        // causal mask (only the diagonal chunk)
        if (kb == qbase) {
            int r0g = qbase + warp * 16 + (lane >> 2);
            int c0 = kb + 2 * (lane & 3);
            #pragma unroll
            for (int j = 0; j < 8; j++) {
                int key = c0 + 8 * j;
                if (key     > r0g)     s[j][0] = -1e30f;
                if (key + 1 > r0g)     s[j][1] = -1e30f;
                if (key     > r0g + 8) s[j][2] = -1e30f;
                if (key + 1 > r0g + 8) s[j][3] = -1e30f;
            }
        }

        // online softmax
        float mx0 = -1e30f, mx1 = -1e30f;
        #pragma unroll
        for (int j = 0; j < 8; j++) {
            mx0 = fmaxf(mx0, fmaxf(s[j][0], s[j][1]));
            mx1 = fmaxf(mx1, fmaxf(s[j][2], s[j][3]));
        }
        mx0 = fmaxf(mx0, __shfl_xor_sync(0xFFFFFFFFu, mx0, 1));
        mx0 = fmaxf(mx0, __shfl_xor_sync(0xFFFFFFFFu, mx0, 2));
        mx1 = fmaxf(mx1, __shfl_xor_sync(0xFFFFFFFFu, mx1, 1));
        mx1 = fmaxf(mx1, __shfl_xor_sync(0xFFFFFFFFu, mx1, 2));
        float nm0 = fmaxf(m0, mx0), nm1 = fmaxf(m1, mx1);
        float c0 = __expf(m0 - nm0), c1 = __expf(m1 - nm1);
        m0 = nm0; m1 = nm1;
        l0 *= c0; l1 *= c1;
        #pragma unroll
        for (int j = 0; j < 8; j++) {
            o[j][0] *= c0; o[j][1] *= c0;
            o[j][2] *= c1; o[j][3] *= c1;
        }
        #pragma unroll
        for (int j = 0; j < 8; j++) {
            s[j][0] = __expf(s[j][0] - nm0); l0 += s[j][0];
            s[j][1] = __expf(s[j][1] - nm0); l0 += s[j][1];
            s[j][2] = __expf(s[j][2] - nm1); l1 += s[j][2];
            s[j][3] = __expf(s[j][3] - nm1); l1 += s[j][3];
        }

        // P -> A fragments (hi/lo): k16 tile t = S n8 tiles 2t, 2t+1
        uint32_t pa[4][4], pb[4][4];
        #pragma unroll
        for (int t = 0; t < 4; t++) {
            split2(s[2*t][0],   s[2*t][1],   pa[t][0], pb[t][0]);
            split2(s[2*t][2],   s[2*t][3],   pa[t][1], pb[t][1]);
            split2(s[2*t+1][0], s[2*t+1][1], pa[t][2], pb[t][2]);
            split2(s[2*t+1][2], s[2*t+1][3], pa[t][3], pb[t][3]);
        }

        // O += P V  (3 split passes); V via ldmatrix.trans (B fragments)
        #pragma unroll
        for (int kt = 0; kt < 4; kt++) {
            uint32_t vf[4][4], vg[4][4];
            #pragma unroll
            for (int hg = 0; hg < 4; hg++) {
                int r = kt * 16 + row_off;
                ldmat_x4t(vf[hg], sVh_u + (uint32_t)((r * KVP + hg*16 + kblk) * 2));
            }
            #pragma unroll
            for (int hg = 0; hg < 4; hg++) {
                uint32_t b0[2] = { vf[hg][0], vf[hg][1] };
                uint32_t b1[2] = { vf[hg][2], vf[hg][3] };
                mma16816(o[2*hg],   pa[kt], b0);
                mma16816(o[2*hg+1], pa[kt], b1);
            }
            #pragma unroll
            for (int hg = 0; hg < 4; hg++) {
                int r = kt * 16 + row_off;
                ldmat_x4t(vg[hg], sVl_u + (uint32_t)((r * KVP + hg*16 + kblk) * 2));
            }
            #pragma unroll
            for (int hg = 0; hg < 4; hg++) {
                uint32_t b0[2] = { vg[hg][0], vg[hg][1] };
                uint32_t b1[2] = { vg[hg][2], vg[hg][3] };
                mma16816(o[2*hg],   pa[kt], b0);
                mma16816(o[2*hg+1], pa[kt], b1);
            }
            #pragma unroll
            for (int hg = 0; hg < 4; hg++) {
                uint32_t b0[2] = { vf[hg][0], vf[hg][1] };
                uint32_t b1[2] = { vf[hg][2], vf[hg][3] };
                mma16816(o[2*hg],   pb[kt], b0);
                mma16816(o[2*hg+1], pb[kt], b1);
            }
        }
    }

    // finalize: quad-reduce l, normalize, write tiled bf16 hi/lo
    l0 += __shfl_xor_sync(0xFFFFFFFFu, l0, 1);
    l0 += __shfl_xor_sync(0xFFFFFFFFu, l0, 2);
    l1 += __shfl_xor_sync(0xFFFFFFFFu, l1, 1);
    l1 += __shfl_xor_sync(0xFFFFFFFFu, l1, 2);
    float i0 = 1.f / l0, i1 = 1.f / l1;

    int row0 = b*TT + qbase + warp * 16 + (lane >> 2);
    #pragma unroll
    for (int j = 0; j < 8; j++) {
        int k = h * HD + 8 * j + 2 * (lane & 3);
        uint32_t hi, lo;
        split2(o[j][0] * i0, o[j][1] * i0, hi, lo);
        size_t off0 = tiled_off(row0, k, DD >> 5);
        *(uint32_t*)(Oh + off0) = hi;
        *(uint32_t*)(Ol + off0) = lo;
        split2(o[j][2] * i1, o[j][3] * i1, hi, lo);
        size_t off1 = tiled_off(row0 + 8, k, DD >> 5);
        *(uint32_t*)(Oh + off1) = hi;
        *(uint32_t*)(Ol + off1) = lo;
    }
}

// ---------------------------------------------------------------------------
// Host orchestration
// ---------------------------------------------------------------------------
template<int MODE, bool SWAPG>
static void launch_gemm(const __nv_bfloat16* Ah, const __nv_bfloat16* Al,
                        const __nv_bfloat16* Bh, const __nv_bfloat16* Bl,
                        const float* bias, const float* res, float* C,
                        __nv_bfloat16* Ch, __nv_bfloat16* Cl,
                        int M, int N, int K)
{
    dim3 grid = SWAPG ? dim3(M / TM, N / TN) : dim3(N / TN, M / TM);
    tc_gemm<MODE, SWAPG><<<grid, NTHR, GEMM_SMEM>>>(M, N, K, Ah, Al, Bh, Bl,
                                                    bias, res, C, Ch, Cl);
}

static void launch_tsplit(const float* W, __nv_bfloat16* Bh, __nv_bfloat16* Bl,
                          int K, int N)
{
    dim3 grid(N / 32, K / 32);
    transpose_split_kernel<<<grid, 256>>>(W, Bh, Bl, K, N);
}

extern "C" void kernel_launch(void* const* d_in, const int* in_sizes, int n_in,
                              void* d_out, int out_size)
{
    const int*   ctx  = (const int*)  d_in[0];
    const float* tok  = (const float*)d_in[1];
    const float* pos  = (const float*)d_in[2];
    const float* Wq   = (const float*)d_in[3];
    const float* Wk   = (const float*)d_in[4];
    const float* Wv   = (const float*)d_in[5];
    const float* Wo   = (const float*)d_in[6];
    const float* bo   = (const float*)d_in[7];
    const float* ln1s = (const float*)d_in[8];
    const float* ln1b = (const float*)d_in[9];
    const float* W1   = (const float*)d_in[10];
    const float* b1   = (const float*)d_in[11];
    const float* W2   = (const float*)d_in[12];
    const float* b2   = (const float*)d_in[13];
    const float* ln2s = (const float*)d_in[14];
    const float* ln2b = (const float*)d_in[15];
    const float* lnfs = (const float*)d_in[16];
    const float* lnfb = (const float*)d_in[17];
    const float* Wout = (const float*)d_in[18];
    const float* bout = (const float*)d_in[19];
    float* out = (float*)d_out;

    cudaFuncSetAttribute(tc_gemm<0,false>,  cudaFuncAttributeMaxDynamicSharedMemorySize, GEMM_SMEM);
    cudaFuncSetAttribute(tc_gemm<3,false>,  cudaFuncAttributeMaxDynamicSharedMemorySize, GEMM_SMEM);
    cudaFuncSetAttribute(tc_gemm<13,false>, cudaFuncAttributeMaxDynamicSharedMemorySize, GEMM_SMEM);
    cudaFuncSetAttribute(tc_gemm<1,true>,   cudaFuncAttributeMaxDynamicSharedMemorySize, GEMM_SMEM);

    float *x, *qkv;
    __nv_bfloat16 *ah, *al, *fh, *fl;
    __nv_bfloat16 *wqkvh, *wqkvl, *woh, *wol, *w1h, *w1l, *w2h, *w2l, *wouth, *woutl;
    cudaGetSymbolAddress((void**)&x,    g_x);
    cudaGetSymbolAddress((void**)&qkv,  g_qkv);
    cudaGetSymbolAddress((void**)&ah,   g_ah);
    cudaGetSymbolAddress((void**)&al,   g_al);
    cudaGetSymbolAddress((void**)&fh,   g_fh);
    cudaGetSymbolAddress((void**)&fl,   g_fl);
    cudaGetSymbolAddress((void**)&wqkvh,g_wqkvh);
    cudaGetSymbolAddress((void**)&wqkvl,g_wqkvl);
    cudaGetSymbolAddress((void**)&woh,  g_woh);
    cudaGetSymbolAddress((void**)&wol,  g_wol);
    cudaGetSymbolAddress((void**)&w1h,  g_w1h);
    cudaGetSymbolAddress((void**)&w1l,  g_w1l);
    cudaGetSymbolAddress((void**)&w2h,  g_w2h);
    cudaGetSymbolAddress((void**)&w2l,  g_w2l);
    cudaGetSymbolAddress((void**)&wouth,g_wouth);
    cudaGetSymbolAddress((void**)&woutl,g_woutl);

    const size_t WQKV_L = (size_t)(QKVD/128)*(DD/32)*5120;
    const size_t WDD_L  = (size_t)(DD/128)*(DD/32)*5120;
    const size_t W1_L   = (size_t)(DFF/128)*(DD/32)*5120;
    const size_t W2_L   = (size_t)(DD/128)*(DFF/32)*5120;

    // Stream index 0: fused layer-0 QKV weight prep
    {
        dim3 grid(DD / 32, DD / 32, 3);
        transpose_split_qkv_kernel<<<grid, 256>>>(Wq, Wk, Wv, wqkvh, wqkvl);
    }
    // Index 1: embedding
    embed_kernel<<<(MM*DD)/256, 256>>>(ctx, tok, pos, x);
    // Index 2: LN1 (layer 0)
    ln_split_kernel<<<MM, 256>>>(x, ln1s, ln1b, ah, al);
    // Index 3: layer-0 QKV GEMM  (-> ncu global index 5)
    launch_gemm<0, false>(ah, al, wqkvh, wqkvl, nullptr, nullptr, qkv,
                          nullptr, nullptr, MM, QKVD, DD);

    // Remaining weight prep
    for (int l = 0; l < LL; l++) {
        if (l > 0) {
            dim3 grid(DD / 32, DD / 32, 3);
            transpose_split_qkv_kernel<<<grid, 256>>>(
                Wq + (size_t)l*DD*DD, Wk + (size_t)l*DD*DD, Wv + (size_t)l*DD*DD,
                wqkvh + (size_t)l*WQKV_L, wqkvl + (size_t)l*WQKV_L);
        }
        launch_tsplit(Wo + (size_t)l*DD*DD,  woh + (size_t)l*WDD_L, wol + (size_t)l*WDD_L, DD, DD);
        launch_tsplit(W1 + (size_t)l*DD*DFF, w1h + (size_t)l*W1_L,  w1l + (size_t)l*W1_L,  DD, DFF);
        launch_tsplit(W2 + (size_t)l*DFF*DD, w2h + (size_t)l*W2_L,  w2l + (size_t)l*W2_L,  DFF, DD);
    }
    launch_tsplit(Wout, wouth, woutl, DD, VV);

    for (int l = 0; l < LL; l++) {
        const __nv_bfloat16* lwqh = wqkvh + (size_t)l*WQKV_L;
        const __nv_bfloat16* lwql = wqkvl + (size_t)l*WQKV_L;
        const __nv_bfloat16* lwoh = woh + (size_t)l*WDD_L;
        const __nv_bfloat16* lwol = wol + (size_t)l*WDD_L;
        const __nv_bfloat16* lw1h = w1h + (size_t)l*W1_L;
        const __nv_bfloat16* lw1l = w1l + (size_t)l*W1_L;
        const __nv_bfloat16* lw2h = w2h + (size_t)l*W2_L;
        const __nv_bfloat16* lw2l = w2l + (size_t)l*W2_L;

        if (l > 0) {
            ln_split_kernel<<<MM, 256>>>(x, ln1s + l*DD, ln1b + l*DD, ah, al);
            launch_gemm<0, false>(ah, al, lwqh, lwql, nullptr, nullptr, qkv,
                                  nullptr, nullptr, MM, QKVD, DD);
        }

        // K/V pre-split then tensor-core attention -> ah/al (tiled bf16 split)
        {
            dim3 gs(TT/128, HH, BB);
            kv_split_kernel<<<gs, 256>>>(qkv);
            dim3 ga(TT/64, HH, BB);
            attn_tc_kernel<<<ga, 128>>>(qkv, ah, al);
        }

        // x = x + att @ Wo + bo
        launch_gemm<3, false>(ah, al, lwoh, lwol, bo + l*DD, x, x,
                              nullptr, nullptr, MM, DD, DD);

        // ah/al = split(LN2(x)); fh/fl = split(relu(ah @ W1 + b1))
        ln_split_kernel<<<MM, 256>>>(x, ln2s + l*DD, ln2b + l*DD, ah, al);
        launch_gemm<13, false>(ah, al, lw1h, lw1l, b1 + l*DFF, nullptr, nullptr,
                               fh, fl, MM, DFF, DD);

        // x = x + fh @ W2 + b2
        launch_gemm<3, false>(fh, fl, lw2h, lw2l, b2 + l*DD, x, x,
                              nullptr, nullptr, MM, DD, DFF);
    }

    // final LN + logits (M-fast rasterization: stream 131MB B once)
    ln_split_kernel<<<MM, 256>>>(x, lnfs, lnfb, ah, al);
    launch_gemm<1, true>(ah, al, wouth, woutl, bout, nullptr, out,
                         nullptr, nullptr, MM, VV, DD);
}